// round 2
// baseline (speedup 1.0000x reference)
#include <cuda_runtime.h>
#include <cuda_bf16.h>

#define N_NODES 100000
#define N_EDGES 3200000
#define IN_DIM  128
#define HID     64

// ---------------- scratch (device globals; no allocation allowed) ----------------
__device__ int    g_is64;                   // 1 if edge_index is int64, 0 if int32
__device__ int    g_deg[N_NODES];
__device__ float  g_dinv[N_NODES];
__device__ int    g_rowptr[N_NODES + 1];
__device__ int    g_cursor[N_NODES];
__device__ float2 g_csr2[N_EDGES];          // (src as int bits, dinv[src])
__device__ float  g_h1[N_NODES * HID];
__device__ float  g_a1[N_NODES * HID];
__device__ float  g_h2[N_NODES * HID];

// ---------------- dtype probe ----------------
// int64 edge ids in [0,100000) => every odd 32-bit word is 0.
// int32 edge ids => odd words are random node ids (P(all zero) ~ 0).
__global__ void detect_kernel(const unsigned* __restrict__ ei32) {
    unsigned o = 0;
    #pragma unroll
    for (int i = 1; i < 128; i += 2) o |= ei32[i];
    g_is64 = (o == 0) ? 1 : 0;
}

__device__ __forceinline__ int edge_at(const void* ei, long long idx) {
    if (g_is64) return (int)((const long long*)ei)[idx];
    return ((const int*)ei)[idx];
}

// ---------------- degree init (self-loop counts as 1) ----------------
__global__ void init_deg_kernel() {
    int i = blockIdx.x * blockDim.x + threadIdx.x;
    if (i < N_NODES) g_deg[i] = 1;
}

// ---------------- dst-degree histogram ----------------
__global__ void hist_kernel(const void* __restrict__ ei) {
    int e = blockIdx.x * blockDim.x + threadIdx.x;
    if (e < N_EDGES) {
        int d = edge_at(ei, (long long)N_EDGES + e);
        atomicAdd(&g_deg[d], 1);
    }
}

// ---------------- single-block scan: rowptr, cursor, dinv ----------------
__global__ void scan_kernel() {
    __shared__ int ssum[1024];
    const int t = threadIdx.x;
    const int CH = (N_NODES + 1023) >> 10;      // 98
    int beg = t * CH;
    int end = beg + CH; if (end > N_NODES) end = N_NODES;
    int s = 0;
    for (int i = beg; i < end; i++) s += g_deg[i] - 1;
    ssum[t] = s;
    __syncthreads();
    if (t == 0) {
        int run = 0;
        for (int j = 0; j < 1024; j++) { int tmp = ssum[j]; ssum[j] = run; run += tmp; }
    }
    __syncthreads();
    int off = ssum[t];
    for (int i = beg; i < end; i++) {
        g_rowptr[i] = off;
        g_cursor[i] = off;
        int dg = g_deg[i];
        g_dinv[i] = rsqrtf((float)dg);
        off += dg - 1;
    }
    if (end == N_NODES && beg <= N_NODES) g_rowptr[N_NODES] = off;
}

// ---------------- counting-sort scatter: build CSR of (src, dinv[src]) ----------------
__global__ void scatter_kernel(const void* __restrict__ ei) {
    int e = blockIdx.x * blockDim.x + threadIdx.x;
    if (e < N_EDGES) {
        int s = edge_at(ei, e);
        int d = edge_at(ei, (long long)N_EDGES + e);
        int pos = atomicAdd(&g_cursor[d], 1);
        g_csr2[pos] = make_float2(__int_as_float(s), g_dinv[s]);
    }
}

// ---------------- tiled GEMM: out[n][o] = sum_k X[n][k]*W[o][k] ----------------
// LAYER 0: X = input x (K=128) -> g_h1.   LAYER 1: X = g_a1 (K=64) -> g_h2.
// Block: 256 threads = 8 warps; warp computes 4 nodes x 64 outputs (2 per lane).
template <int LAYER>
__global__ void gemm_kernel(const float* __restrict__ Xin, const float* __restrict__ W) {
    constexpr int K = (LAYER == 0) ? IN_DIM : HID;
    const float* __restrict__ X = (LAYER == 0) ? Xin : g_a1;
    float* __restrict__ out     = (LAYER == 0) ? g_h1 : g_h2;

    __shared__ __align__(16) float Ws[64 * 66];   // [kk][o] transposed, padded
    __shared__ __align__(16) float Xs[32 * 64];   // [node_local][kk]

    const int tid  = threadIdx.x;
    const int warp = tid >> 5, lane = tid & 31;
    const int node0 = blockIdx.x * 32;

    float2 acc[4];
    #pragma unroll
    for (int r = 0; r < 4; r++) acc[r] = make_float2(0.f, 0.f);

    #pragma unroll
    for (int kt = 0; kt < K; kt += 64) {
        // load W tile (coalesced global read, transposed smem write)
        #pragma unroll
        for (int i = tid; i < 64 * 64; i += 256) {
            int o = i >> 6, kk = i & 63;
            Ws[kk * 66 + o] = W[o * K + kt + kk];
        }
        // load X tile
        #pragma unroll
        for (int i = tid; i < 32 * 64; i += 256) {
            int nl = i >> 6, kk = i & 63;
            Xs[nl * 64 + kk] = X[(node0 + nl) * K + kt + kk];
        }
        __syncthreads();
        #pragma unroll 8
        for (int kk = 0; kk < 64; kk++) {
            float2 w = *(const float2*)&Ws[kk * 66 + 2 * lane];
            #pragma unroll
            for (int r = 0; r < 4; r++) {
                float xv = Xs[(warp * 4 + r) * 64 + kk];
                acc[r].x = fmaf(xv, w.x, acc[r].x);
                acc[r].y = fmaf(xv, w.y, acc[r].y);
            }
        }
        __syncthreads();
    }
    #pragma unroll
    for (int r = 0; r < 4; r++) {
        int node = node0 + warp * 4 + r;
        ((float2*)out)[node * 32 + lane] = acc[r];
    }
}

// ---------------- warp-per-node aggregation core ----------------
// returns dinv[i]*sum_{e in CSR[i]}(dinv[s]*h[s]) + dinv[i]^2*h[i]   (2 channels/lane)
__device__ __forceinline__ float2 agg_body(int node, int lane, const float* __restrict__ h) {
    const float2* __restrict__ h2 = (const float2*)h;
    int rbeg = g_rowptr[node];
    int rend = g_rowptr[node + 1];
    float2 acc = make_float2(0.f, 0.f);
    #pragma unroll 4
    for (int e = rbeg; e < rend; e++) {
        float2 ent = g_csr2[e];                 // uniform address: broadcast
        int   s  = __float_as_int(ent.x);
        float ns = ent.y;
        float2 v = h2[s * 32 + lane];           // 256B row gather (L2-resident)
        acc.x = fmaf(ns, v.x, acc.x);
        acc.y = fmaf(ns, v.y, acc.y);
    }
    float di  = g_dinv[node];
    float dii = di * di;
    float2 sv = h2[node * 32 + lane];
    acc.x = fmaf(di, acc.x, dii * sv.x);
    acc.y = fmaf(di, acc.y, dii * sv.y);
    return acc;
}

// layer-1 aggregation: a1 = relu(agg(h1) + b1)
__global__ void agg_relu_kernel(const float* __restrict__ b1) {
    int warp = threadIdx.x >> 5, lane = threadIdx.x & 31;
    int node = blockIdx.x * 8 + warp;
    if (node >= N_NODES) return;
    float2 acc = agg_body(node, lane, g_h1);
    float2 bb = ((const float2*)b1)[lane];
    float2 o;
    o.x = fmaxf(acc.x + bb.x, 0.f);
    o.y = fmaxf(acc.y + bb.y, 0.f);
    ((float2*)g_a1)[node * 32 + lane] = o;
}

// layer-2 aggregation fused with classifier: out[i] = dot(agg(h2)+b2, Wc) + bc
__global__ void agg_final_kernel(const float* __restrict__ b2,
                                 const float* __restrict__ Wc,
                                 const float* __restrict__ bc,
                                 float* __restrict__ out) {
    int warp = threadIdx.x >> 5, lane = threadIdx.x & 31;
    int node = blockIdx.x * 8 + warp;
    if (node >= N_NODES) return;
    float2 acc = agg_body(node, lane, g_h2);
    float2 bb = ((const float2*)b2)[lane];
    float2 wc = ((const float2*)Wc)[lane];
    float p = (acc.x + bb.x) * wc.x + (acc.y + bb.y) * wc.y;
    #pragma unroll
    for (int o = 16; o > 0; o >>= 1) p += __shfl_xor_sync(0xffffffffu, p, o);
    if (lane == 0) out[node] = p + bc[0];
}

// ---------------- launch ----------------
extern "C" void kernel_launch(void* const* d_in, const int* in_sizes, int n_in,
                              void* d_out, int out_size) {
    const float* x  = (const float*)d_in[0];
    const void*  ei = d_in[1];                 // int32 or int64, probed on device
    const float* W1 = (const float*)d_in[2];
    const float* b1 = (const float*)d_in[3];
    const float* W2 = (const float*)d_in[4];
    const float* b2 = (const float*)d_in[5];
    const float* Wc = (const float*)d_in[6];
    const float* bc = (const float*)d_in[7];
    float* out = (float*)d_out;

    detect_kernel<<<1, 1>>>((const unsigned*)ei);
    init_deg_kernel<<<(N_NODES + 511) / 512, 512>>>();
    hist_kernel<<<N_EDGES / 256, 256>>>(ei);
    scan_kernel<<<1, 1024>>>();
    scatter_kernel<<<N_EDGES / 256, 256>>>(ei);

    gemm_kernel<0><<<N_NODES / 32, 256>>>(x, W1);
    agg_relu_kernel<<<(N_NODES + 7) / 8, 256>>>(b1);
    gemm_kernel<1><<<N_NODES / 32, 256>>>(x /*unused*/, W2);
    agg_final_kernel<<<(N_NODES + 7) / 8, 256>>>(b2, Wc, bc, out);
}

// round 3
// speedup vs baseline: 1.7084x; 1.7084x over previous
#include <cuda_runtime.h>
#include <cuda_bf16.h>

#define N_NODES 100000
#define N_EDGES 3200000
#define IN_DIM  128
#define HID     64

#define SCAN_B  512
#define SCAN_NB ((N_NODES + SCAN_B - 1) / SCAN_B)   // 196

// ---------------- scratch (device globals; no allocation allowed) ----------------
__device__ int    g_is64;                   // 1 if edge_index is int64, 0 if int32
__device__ int    g_deg[N_NODES];
__device__ float  g_dinv[N_NODES];
__device__ int    g_rowptr[N_NODES + 1];
__device__ int    g_cursor[N_NODES];
__device__ int    g_scan[N_NODES];
__device__ int    g_bsum[SCAN_NB];
__device__ int    g_boff[SCAN_NB];
__device__ float2 g_csr2[N_EDGES];          // (src as int bits, dinv[src])
__device__ float  g_h1[N_NODES * HID];
__device__ float  g_a1[N_NODES * HID];
__device__ float  g_h2[N_NODES * HID];

// ---------------- dtype probe ----------------
// int64 edge ids in [0,100000) => every odd 32-bit word is 0.
__global__ void detect_kernel(const unsigned* __restrict__ ei32) {
    unsigned o = 0;
    #pragma unroll
    for (int i = 1; i < 128; i += 2) o |= ei32[i];
    g_is64 = (o == 0) ? 1 : 0;
}

__device__ __forceinline__ int edge_at(const void* ei, long long idx) {
    if (g_is64) return (int)((const long long*)ei)[idx];
    return ((const int*)ei)[idx];
}

// ---------------- degree init (self-loop counts as 1) ----------------
__global__ void init_deg_kernel() {
    int i = blockIdx.x * blockDim.x + threadIdx.x;
    if (i < N_NODES) g_deg[i] = 1;
}

// ---------------- dst-degree histogram ----------------
__global__ void hist_kernel(const void* __restrict__ ei) {
    int e = blockIdx.x * blockDim.x + threadIdx.x;
    if (e < N_EDGES) {
        int d = edge_at(ei, (long long)N_EDGES + e);
        atomicAdd(&g_deg[d], 1);
    }
}

// ---------------- parallel 3-phase exclusive scan of (deg-1) ----------------
__global__ void scan1_kernel() {
    __shared__ int wsum[16];
    const int tid  = threadIdx.x;
    const int lane = tid & 31, warp = tid >> 5;
    const int i = blockIdx.x * SCAN_B + tid;
    int v = (i < N_NODES) ? (g_deg[i] - 1) : 0;
    // warp inclusive scan
    int s = v;
    #pragma unroll
    for (int o = 1; o < 32; o <<= 1) {
        int t = __shfl_up_sync(0xffffffffu, s, o);
        if (lane >= o) s += t;
    }
    if (lane == 31) wsum[warp] = s;
    __syncthreads();
    if (warp == 0) {
        int ws = (lane < 16) ? wsum[lane] : 0;
        #pragma unroll
        for (int o = 1; o < 16; o <<= 1) {
            int t = __shfl_up_sync(0xffffffffu, ws, o);
            if (lane >= o) ws += t;
        }
        if (lane < 16) wsum[lane] = ws;
    }
    __syncthreads();
    int excl = s - v + (warp ? wsum[warp - 1] : 0);
    if (i < N_NODES) g_scan[i] = excl;
    if (tid == SCAN_B - 1) g_bsum[blockIdx.x] = excl + v;   // block total
}

__global__ void scan2_kernel() {       // 1 block, 256 threads (>=196)
    __shared__ int sh[256];
    const int t = threadIdx.x;
    int v0 = (t < SCAN_NB) ? g_bsum[t] : 0;
    sh[t] = v0;
    __syncthreads();
    #pragma unroll
    for (int o = 1; o < 256; o <<= 1) {
        int v = (t >= o) ? sh[t - o] : 0;
        __syncthreads();
        sh[t] += v;
        __syncthreads();
    }
    if (t < SCAN_NB) g_boff[t] = sh[t] - v0;   // exclusive
}

__global__ void scan3_kernel() {
    int i = blockIdx.x * blockDim.x + threadIdx.x;
    if (i < N_NODES) {
        int off = g_scan[i] + g_boff[i / SCAN_B];
        g_rowptr[i] = off;
        g_cursor[i] = off;
        g_dinv[i]   = rsqrtf((float)g_deg[i]);
    }
    if (i == 0) g_rowptr[N_NODES] = N_EDGES;   // sum(deg-1) == E
}

// ---------------- counting-sort scatter: build CSR of (src, dinv[src]) ----------------
__global__ void scatter_kernel(const void* __restrict__ ei) {
    int e = blockIdx.x * blockDim.x + threadIdx.x;
    if (e < N_EDGES) {
        int s = edge_at(ei, e);
        int d = edge_at(ei, (long long)N_EDGES + e);
        int pos = atomicAdd(&g_cursor[d], 1);
        g_csr2[pos] = make_float2(__int_as_float(s), g_dinv[s]);
    }
}

// ---------------- tiled GEMM: out[n][o] = sum_k X[n][k]*W[o][k] ----------------
template <int LAYER>
__global__ void gemm_kernel(const float* __restrict__ Xin, const float* __restrict__ W) {
    constexpr int K = (LAYER == 0) ? IN_DIM : HID;
    const float* __restrict__ X = (LAYER == 0) ? Xin : g_a1;
    float* __restrict__ out     = (LAYER == 0) ? g_h1 : g_h2;

    __shared__ __align__(16) float Ws[64 * 66];   // [kk][o] transposed, padded
    __shared__ __align__(16) float Xs[32 * 64];   // [node_local][kk]

    const int tid  = threadIdx.x;
    const int warp = tid >> 5, lane = tid & 31;
    const int node0 = blockIdx.x * 32;

    float2 acc[4];
    #pragma unroll
    for (int r = 0; r < 4; r++) acc[r] = make_float2(0.f, 0.f);

    #pragma unroll
    for (int kt = 0; kt < K; kt += 64) {
        #pragma unroll
        for (int i = tid; i < 64 * 64; i += 256) {
            int o = i >> 6, kk = i & 63;
            Ws[kk * 66 + o] = W[o * K + kt + kk];
        }
        #pragma unroll
        for (int i = tid; i < 32 * 64; i += 256) {
            int nl = i >> 6, kk = i & 63;
            Xs[nl * 64 + kk] = X[(node0 + nl) * K + kt + kk];
        }
        __syncthreads();
        #pragma unroll 8
        for (int kk = 0; kk < 64; kk++) {
            float2 w = *(const float2*)&Ws[kk * 66 + 2 * lane];
            #pragma unroll
            for (int r = 0; r < 4; r++) {
                float xv = Xs[(warp * 4 + r) * 64 + kk];
                acc[r].x = fmaf(xv, w.x, acc[r].x);
                acc[r].y = fmaf(xv, w.y, acc[r].y);
            }
        }
        __syncthreads();
    }
    #pragma unroll
    for (int r = 0; r < 4; r++) {
        int node = node0 + warp * 4 + r;
        ((float2*)out)[node * 32 + lane] = acc[r];
    }
}

// ---------------- warp-per-node aggregation core ----------------
__device__ __forceinline__ float2 agg_body(int node, int lane, const float* __restrict__ h) {
    const float2* __restrict__ h2 = (const float2*)h;
    int rbeg = g_rowptr[node];
    int rend = g_rowptr[node + 1];
    float2 acc = make_float2(0.f, 0.f);
    #pragma unroll 4
    for (int e = rbeg; e < rend; e++) {
        float2 ent = g_csr2[e];                 // uniform address: broadcast
        int   s  = __float_as_int(ent.x);
        float ns = ent.y;
        float2 v = h2[s * 32 + lane];           // 256B row gather (L2-resident)
        acc.x = fmaf(ns, v.x, acc.x);
        acc.y = fmaf(ns, v.y, acc.y);
    }
    float di  = g_dinv[node];
    float dii = di * di;
    float2 sv = h2[node * 32 + lane];
    acc.x = fmaf(di, acc.x, dii * sv.x);
    acc.y = fmaf(di, acc.y, dii * sv.y);
    return acc;
}

// layer-1 aggregation: a1 = relu(agg(h1) + b1)
__global__ void agg_relu_kernel(const float* __restrict__ b1) {
    int warp = threadIdx.x >> 5, lane = threadIdx.x & 31;
    int node = blockIdx.x * 8 + warp;
    if (node >= N_NODES) return;
    float2 acc = agg_body(node, lane, g_h1);
    float2 bb = ((const float2*)b1)[lane];
    float2 o;
    o.x = fmaxf(acc.x + bb.x, 0.f);
    o.y = fmaxf(acc.y + bb.y, 0.f);
    ((float2*)g_a1)[node * 32 + lane] = o;
}

// layer-2 aggregation fused with classifier: out[i] = dot(agg(h2)+b2, Wc) + bc
__global__ void agg_final_kernel(const float* __restrict__ b2,
                                 const float* __restrict__ Wc,
                                 const float* __restrict__ bc,
                                 float* __restrict__ out) {
    int warp = threadIdx.x >> 5, lane = threadIdx.x & 31;
    int node = blockIdx.x * 8 + warp;
    if (node >= N_NODES) return;
    float2 acc = agg_body(node, lane, g_h2);
    float2 bb = ((const float2*)b2)[lane];
    float2 wc = ((const float2*)Wc)[lane];
    float p = (acc.x + bb.x) * wc.x + (acc.y + bb.y) * wc.y;
    #pragma unroll
    for (int o = 16; o > 0; o >>= 1) p += __shfl_xor_sync(0xffffffffu, p, o);
    if (lane == 0) out[node] = p + bc[0];
}

// ---------------- launch ----------------
extern "C" void kernel_launch(void* const* d_in, const int* in_sizes, int n_in,
                              void* d_out, int out_size) {
    const float* x  = (const float*)d_in[0];
    const void*  ei = d_in[1];                 // int32 or int64, probed on device
    const float* W1 = (const float*)d_in[2];
    const float* b1 = (const float*)d_in[3];
    const float* W2 = (const float*)d_in[4];
    const float* b2 = (const float*)d_in[5];
    const float* Wc = (const float*)d_in[6];
    const float* bc = (const float*)d_in[7];
    float* out = (float*)d_out;

    detect_kernel<<<1, 1>>>((const unsigned*)ei);
    init_deg_kernel<<<(N_NODES + 511) / 512, 512>>>();
    hist_kernel<<<N_EDGES / 256, 256>>>(ei);
    scan1_kernel<<<SCAN_NB, SCAN_B>>>();
    scan2_kernel<<<1, 256>>>();
    scan3_kernel<<<(N_NODES + 511) / 512, 512>>>();
    scatter_kernel<<<N_EDGES / 256, 256>>>(ei);

    gemm_kernel<0><<<N_NODES / 32, 256>>>(x, W1);
    agg_relu_kernel<<<(N_NODES + 7) / 8, 256>>>(b1);
    gemm_kernel<1><<<N_NODES / 32, 256>>>(x /*unused*/, W2);
    agg_final_kernel<<<(N_NODES + 7) / 8, 256>>>(b2, Wc, bc, out);
}

// round 4
// speedup vs baseline: 2.3353x; 1.3670x over previous
#include <cuda_runtime.h>
#include <cuda_bf16.h>

#define N_NODES 100000
#define N_EDGES 3200000
#define IN_DIM  128
#define HID     64

#define SCAN_B  512
#define SCAN_NB ((N_NODES + SCAN_B - 1) / SCAN_B)   // 196

// ---------------- scratch (device globals; no allocation allowed) ----------------
__device__ int    g_is64;                   // 1 if edge_index is int64, 0 if int32
__device__ int    g_deg[N_NODES];
__device__ float  g_dinv[N_NODES];
__device__ int    g_rowptr[N_NODES + 1];
__device__ int    g_cursor[N_NODES];
__device__ int    g_scan[N_NODES];
__device__ int    g_bsum[SCAN_NB];
__device__ int    g_boff[SCAN_NB];
__device__ int    g_csr[N_EDGES];           // src index only
__device__ float  g_h1[N_NODES * HID];      // h1' = dinv * (x @ W1^T)
__device__ float  g_z[N_NODES];             // z'  = dinv * (a1 . w)
__device__ float  g_w[HID];                 // w = W2^T @ Wc
__device__ float  g_cb;                     // b2.Wc + bc

// ---------------- dtype probe ----------------
// int64 edge ids in [0,100000) => every odd 32-bit word is 0.
__global__ void detect_kernel(const unsigned* __restrict__ ei32) {
    unsigned o = 0;
    #pragma unroll
    for (int i = 1; i < 128; i += 2) o |= ei32[i];
    g_is64 = (o == 0) ? 1 : 0;
}

__device__ __forceinline__ int edge_at(const void* ei, long long idx) {
    if (g_is64) return (int)((const long long*)ei)[idx];
    return ((const int*)ei)[idx];
}

// ---------------- degree init (self-loop counts as 1) ----------------
__global__ void init_deg_kernel() {
    int i = blockIdx.x * blockDim.x + threadIdx.x;
    if (i < N_NODES) g_deg[i] = 1;
}

// ---------------- dst-degree histogram ----------------
__global__ void hist_kernel(const void* __restrict__ ei) {
    int e = blockIdx.x * blockDim.x + threadIdx.x;
    if (e < N_EDGES) {
        int d = edge_at(ei, (long long)N_EDGES + e);
        atomicAdd(&g_deg[d], 1);
    }
}

// ---------------- parallel 3-phase exclusive scan of (deg-1) ----------------
__global__ void scan1_kernel() {
    __shared__ int wsum[16];
    const int tid  = threadIdx.x;
    const int lane = tid & 31, warp = tid >> 5;
    const int i = blockIdx.x * SCAN_B + tid;
    int v = (i < N_NODES) ? (g_deg[i] - 1) : 0;
    int s = v;
    #pragma unroll
    for (int o = 1; o < 32; o <<= 1) {
        int t = __shfl_up_sync(0xffffffffu, s, o);
        if (lane >= o) s += t;
    }
    if (lane == 31) wsum[warp] = s;
    __syncthreads();
    if (warp == 0) {
        int ws = (lane < 16) ? wsum[lane] : 0;
        #pragma unroll
        for (int o = 1; o < 16; o <<= 1) {
            int t = __shfl_up_sync(0xffffffffu, ws, o);
            if (lane >= o) ws += t;
        }
        if (lane < 16) wsum[lane] = ws;
    }
    __syncthreads();
    int excl = s - v + (warp ? wsum[warp - 1] : 0);
    if (i < N_NODES) g_scan[i] = excl;
    if (tid == SCAN_B - 1) g_bsum[blockIdx.x] = excl + v;
}

__global__ void scan2_kernel() {       // 1 block, 256 threads (>=196)
    __shared__ int sh[256];
    const int t = threadIdx.x;
    int v0 = (t < SCAN_NB) ? g_bsum[t] : 0;
    sh[t] = v0;
    __syncthreads();
    #pragma unroll
    for (int o = 1; o < 256; o <<= 1) {
        int v = (t >= o) ? sh[t - o] : 0;
        __syncthreads();
        sh[t] += v;
        __syncthreads();
    }
    if (t < SCAN_NB) g_boff[t] = sh[t] - v0;
}

__global__ void scan3_kernel() {
    int i = blockIdx.x * blockDim.x + threadIdx.x;
    if (i < N_NODES) {
        int off = g_scan[i] + g_boff[i / SCAN_B];
        g_rowptr[i] = off;
        g_cursor[i] = off;
        g_dinv[i]   = rsqrtf((float)g_deg[i]);
    }
    if (i == 0) g_rowptr[N_NODES] = N_EDGES;   // sum(deg-1) == E
}

// ---------------- counting-sort scatter: CSR of src indices ----------------
__global__ void scatter_kernel(const void* __restrict__ ei) {
    int e = blockIdx.x * blockDim.x + threadIdx.x;
    if (e < N_EDGES) {
        int s = edge_at(ei, e);
        int d = edge_at(ei, (long long)N_EDGES + e);
        int pos = atomicAdd(&g_cursor[d], 1);
        g_csr[pos] = s;
    }
}

// ---------------- classifier fold: w = W2^T @ Wc, cb = b2.Wc + bc ----------------
__global__ void wprep_kernel(const float* __restrict__ W2,
                             const float* __restrict__ b2,
                             const float* __restrict__ Wc,
                             const float* __restrict__ bc) {
    int k = threadIdx.x;              // 64 threads
    float s = 0.f;
    #pragma unroll
    for (int j = 0; j < HID; j++) s = fmaf(Wc[j], W2[j * HID + k], s);
    g_w[k] = s;
    if (k == 0) {
        float c = bc[0];
        #pragma unroll
        for (int j = 0; j < HID; j++) c = fmaf(b2[j], Wc[j], c);
        g_cb = c;
    }
}

// ---------------- GEMM1: h1'[n][o] = dinv[n] * sum_k x[n][k]*W1[o][k] ----------------
// Block: 256 threads = 8 warps; warp computes 4 nodes x 64 outputs (2 per lane).
__global__ void gemm1_kernel(const float* __restrict__ X, const float* __restrict__ W) {
    __shared__ __align__(16) float Ws[64 * 66];   // [kk][o] transposed, padded
    __shared__ __align__(16) float Xs[32 * 64];   // [node_local][kk]

    const int tid  = threadIdx.x;
    const int warp = tid >> 5, lane = tid & 31;
    const int node0 = blockIdx.x * 32;

    float2 acc[4];
    #pragma unroll
    for (int r = 0; r < 4; r++) acc[r] = make_float2(0.f, 0.f);

    #pragma unroll
    for (int kt = 0; kt < IN_DIM; kt += 64) {
        #pragma unroll
        for (int i = tid; i < 64 * 64; i += 256) {
            int o = i >> 6, kk = i & 63;
            Ws[kk * 66 + o] = W[o * IN_DIM + kt + kk];
        }
        #pragma unroll
        for (int i = tid; i < 32 * 64; i += 256) {
            int nl = i >> 6, kk = i & 63;
            Xs[nl * 64 + kk] = X[(node0 + nl) * IN_DIM + kt + kk];
        }
        __syncthreads();
        #pragma unroll 8
        for (int kk = 0; kk < 64; kk++) {
            float2 w = *(const float2*)&Ws[kk * 66 + 2 * lane];
            #pragma unroll
            for (int r = 0; r < 4; r++) {
                float xv = Xs[(warp * 4 + r) * 64 + kk];
                acc[r].x = fmaf(xv, w.x, acc[r].x);
                acc[r].y = fmaf(xv, w.y, acc[r].y);
            }
        }
        __syncthreads();
    }
    #pragma unroll
    for (int r = 0; r < 4; r++) {
        int node = node0 + warp * 4 + r;
        float di = g_dinv[node];
        acc[r].x *= di; acc[r].y *= di;
        ((float2*)g_h1)[node * 32 + lane] = acc[r];
    }
}

// ---------------- agg1 fused with layer-2 channel fold ----------------
// a1[d] = relu(dinv_d*(sum_s h1'[s] + h1'[d]) + b1);  z'[d] = dinv_d * (a1[d].w)
__global__ void agg1_kernel(const float* __restrict__ b1) {
    int warp = threadIdx.x >> 5, lane = threadIdx.x & 31;
    int node = blockIdx.x * 8 + warp;
    if (node >= N_NODES) return;

    const float2* __restrict__ h2 = (const float2*)g_h1;
    int rbeg = g_rowptr[node];
    int rend = g_rowptr[node + 1];
    float2 acc = make_float2(0.f, 0.f);
    #pragma unroll 4
    for (int e = rbeg; e < rend; e++) {
        int s = g_csr[e];                        // uniform: broadcast
        float2 v = h2[s * 32 + lane];            // 256B row gather (L2-resident)
        acc.x += v.x;
        acc.y += v.y;
    }
    float2 sv = h2[node * 32 + lane];            // self term (h1' already dinv-scaled)
    acc.x += sv.x;
    acc.y += sv.y;

    float di = g_dinv[node];
    float2 bb = ((const float2*)b1)[lane];
    float ax = fmaxf(fmaf(di, acc.x, bb.x), 0.f);
    float ay = fmaxf(fmaf(di, acc.y, bb.y), 0.f);

    float2 wv = ((const float2*)g_w)[lane];
    float p = ax * wv.x + ay * wv.y;
    #pragma unroll
    for (int o = 16; o > 0; o >>= 1) p += __shfl_xor_sync(0xffffffffu, p, o);
    if (lane == 0) g_z[node] = di * p;           // z' = dinv * (a1 . w)
}

// ---------------- agg2 (scalar): out[d] = dinv_d*(sum_s z'[s] + z'[d]) + cb ----------------
__global__ void agg2_kernel(float* __restrict__ out) {
    int warp = threadIdx.x >> 5, lane = threadIdx.x & 31;
    int node = blockIdx.x * 8 + warp;
    if (node >= N_NODES) return;

    int rbeg = g_rowptr[node];
    int rend = g_rowptr[node + 1];
    float acc = 0.f;
    for (int e = rbeg + lane; e < rend; e += 32) {
        acc += g_z[g_csr[e]];                    // 4B gather in 400KB table
    }
    #pragma unroll
    for (int o = 16; o > 0; o >>= 1) acc += __shfl_xor_sync(0xffffffffu, acc, o);
    if (lane == 0) out[node] = fmaf(g_dinv[node], acc + g_z[node], 1.f * 0.f) + g_cb
                               + g_dinv[node] * 0.f;   // keep simple: computed below
}

// cleaner version of the final line above (avoid the dummy arithmetic)
__global__ void agg2b_kernel(float* __restrict__ out) {
    int warp = threadIdx.x >> 5, lane = threadIdx.x & 31;
    int node = blockIdx.x * 8 + warp;
    if (node >= N_NODES) return;

    int rbeg = g_rowptr[node];
    int rend = g_rowptr[node + 1];
    float acc = 0.f;
    for (int e = rbeg + lane; e < rend; e += 32) {
        acc += g_z[g_csr[e]];
    }
    #pragma unroll
    for (int o = 16; o > 0; o >>= 1) acc += __shfl_xor_sync(0xffffffffu, acc, o);
    if (lane == 0) out[node] = g_dinv[node] * (acc + g_z[node]) + g_cb;
}

// ---------------- launch ----------------
extern "C" void kernel_launch(void* const* d_in, const int* in_sizes, int n_in,
                              void* d_out, int out_size) {
    const float* x  = (const float*)d_in[0];
    const void*  ei = d_in[1];                 // int32 or int64, probed on device
    const float* W1 = (const float*)d_in[2];
    const float* b1 = (const float*)d_in[3];
    const float* W2 = (const float*)d_in[4];
    const float* b2 = (const float*)d_in[5];
    const float* Wc = (const float*)d_in[6];
    const float* bc = (const float*)d_in[7];
    float* out = (float*)d_out;

    detect_kernel<<<1, 1>>>((const unsigned*)ei);
    init_deg_kernel<<<(N_NODES + 511) / 512, 512>>>();
    hist_kernel<<<N_EDGES / 256, 256>>>(ei);
    scan1_kernel<<<SCAN_NB, SCAN_B>>>();
    scan2_kernel<<<1, 256>>>();
    scan3_kernel<<<(N_NODES + 511) / 512, 512>>>();
    scatter_kernel<<<N_EDGES / 256, 256>>>(ei);

    wprep_kernel<<<1, 64>>>(W2, b2, Wc, bc);
    gemm1_kernel<<<N_NODES / 32, 256>>>(x, W1);
    agg1_kernel<<<(N_NODES + 7) / 8, 256>>>(b1);
    agg2b_kernel<<<(N_NODES + 7) / 8, 256>>>(out);
}